// round 9
// baseline (speedup 1.0000x reference)
#include <cuda_runtime.h>
#include <cuda_bf16.h>

// WTA2D: per (B,C) row of H*W=3136 fp32, t = 313th-largest, out = (t > x) ? x : 0.
//
// One CTA (256 thr) per row. 12 raw uint keys/thread in registers + 64
// remainder elems in shared (urem). Iterated 256-bucket shared atomic byte
// histogram (raw domain, sign fold via XOR mask X) resolves 8 bits/round;
// exit to a <=64-candidate gather + warp-0 ballot bisection as soon as the
// crossing bucket fits, or after 4 rounds the full raw threshold is resolved.
// Tiny smem footprint + __launch_bounds__(256,8) -> 8 CTAs/SM to hide the
// serial pick/bisect phases.

#define NROW 3136
#define KSEL 313u

__device__ __forceinline__ unsigned u2k(unsigned u) {
    return (u & 0x80000000u) ? ~u : (u | 0x80000000u);
}
__device__ __forceinline__ float k2f(unsigned k) {
    unsigned u = (k & 0x80000000u) ? (k ^ 0x80000000u) : ~k;
    return __uint_as_float(u);
}

__global__ void __launch_bounds__(256, 8)
wta2d_kernel(const float* __restrict__ x, float* __restrict__ out) {
    const int tid  = threadIdx.x;
    const int lane = tid & 31;
    const int warp = tid >> 5;
    const size_t base = (size_t)blockIdx.x * NROW;

    __shared__ unsigned hist[256];
    __shared__ uint4 urem4[16];            // last 64 elements (raw bits)
    __shared__ unsigned gbuf[64];
    __shared__ unsigned sb_d, sb_rank, sb_m;
    __shared__ float sb_t;
    __shared__ int gcount;

    hist[tid] = 0u;
    if (tid == 0) gcount = 0;

    // ---- load row: 12 keys in regs + 64 remainder to shared ----
    unsigned u[12];
    const uint4* xin = reinterpret_cast<const uint4*>(x + base);
#pragma unroll
    for (int s = 0; s < 3; ++s) {
        uint4 f = xin[tid + s * 256];
        u[4*s+0] = f.x; u[4*s+1] = f.y; u[4*s+2] = f.z; u[4*s+3] = f.w;
    }
    if (tid < 16) urem4[tid] = xin[768 + tid];
    __syncthreads();                        // zeros + urem visible

    unsigned myrem = 0u;
    if (tid < 64) myrem = reinterpret_cast<const unsigned*>(urem4)[tid];

    // ---- round 1: raw top-byte histogram ----
#pragma unroll
    for (int j = 0; j < 12; ++j) atomicAdd(&hist[u[j] >> 24], 1u);
    if (tid < 64) atomicAdd(&hist[myrem >> 24], 1u);
    __syncthreads();

    if (warp == 0) {
        // ordered slot o (0 = highest key): o<128 -> u8=127-o (positives
        // descending), o>=128 -> u8=o (negatives descending).
        int o0 = lane * 8;
        unsigned cc[8];
#pragma unroll
        for (int j = 0; j < 8; ++j) {
            int o = o0 + j;
            int u8 = (o < 128) ? (127 - o) : o;
            cc[j] = hist[u8];
        }
        unsigned tot = cc[0]+cc[1]+cc[2]+cc[3]+cc[4]+cc[5]+cc[6]+cc[7];
        unsigned p = tot;                   // inclusive prefix over lanes
#pragma unroll
        for (int off = 1; off <= 16; off <<= 1) {
            unsigned v = __shfl_up_sync(0xFFFFFFFFu, p, off);
            if (lane >= off) p += v;
        }
        unsigned run = p - tot;             // counts in lower-o (higher-key) slots
#pragma unroll
        for (int j = 0; j < 8; ++j) {
            unsigned nr = run + cc[j];
            if (nr >= KSEL && run < KSEL) {
                int o = o0 + j;
                unsigned u8 = (o < 128) ? (unsigned)(127 - o) : (unsigned)o;
                sb_d    = u8 | ((o >= 128) ? 256u : 0u);  // bit8 = negative region
                sb_rank = KSEL - run;
                sb_m    = cc[j];
            }
            run = nr;
        }
    }
    __syncthreads();

    const unsigned X = (sb_d & 256u) ? 0xFFu : 0u;  // lower-byte sign fold
    unsigned U  = sb_d & 0xFFu;                     // raw prefix
    unsigned K  = X ? (255u - U) : (U + 128u);      // key prefix
    unsigned rk = sb_rank;
    unsigned m  = sb_m;
    int bits = 24;                                  // unresolved low bits

    // ---- rounds 2..4: iterate byte histogram while bucket too big ----
    while (m > 64u && bits > 0) {
        hist[tid] = 0u;
        __syncthreads();
#pragma unroll
        for (int j = 0; j < 12; ++j)
            if ((u[j] >> bits) == U)
                atomicAdd(&hist[((u[j] >> (bits - 8)) & 0xFFu) ^ X], 1u);
        if (tid < 64 && (myrem >> bits) == U)
            atomicAdd(&hist[((myrem >> (bits - 8)) & 0xFFu) ^ X], 1u);
        __syncthreads();
        if (warp == 0) {                    // descending pick (key-byte order)
            unsigned rcur = rk;
            const uint4* h4 = reinterpret_cast<const uint4*>(hist) + lane * 2;
            uint4 v0 = h4[0], v1 = h4[1];
            unsigned cc[8] = { v0.x, v0.y, v0.z, v0.w, v1.x, v1.y, v1.z, v1.w };
            unsigned tot = cc[0]+cc[1]+cc[2]+cc[3]+cc[4]+cc[5]+cc[6]+cc[7];
            unsigned s = tot;
#pragma unroll
            for (int off = 1; off <= 16; off <<= 1) {
                unsigned v = __shfl_down_sync(0xFFFFFFFFu, s, off);
                if (lane + off < 32) s += v;
            }
            unsigned run = s - tot;         // counts in higher-key buckets
#pragma unroll
            for (int j = 7; j >= 0; --j) {
                unsigned nr = run + cc[j];
                if (nr >= rcur && run < rcur) {
                    sb_d    = (unsigned)(lane * 8 + j);   // key byte
                    sb_rank = rcur - run;
                    sb_m    = cc[j];
                }
                run = nr;
            }
        }
        __syncthreads();
        unsigned d = sb_d;
        U  = (U << 8) | (d ^ X);
        K  = (K << 8) | d;
        rk = sb_rank;
        m  = sb_m;
        bits -= 8;
    }

    // ---- tail ----
    if (bits > 0) {
        // m <= 64 here: gather candidates (keys computed only for these)
#pragma unroll
        for (int j = 0; j < 12; ++j)
            if ((u[j] >> bits) == U) gbuf[atomicAdd(&gcount, 1)] = u2k(u[j]);
        if (tid < 64 && (myrem >> bits) == U)
            gbuf[atomicAdd(&gcount, 1)] = u2k(myrem);
        __syncthreads();
        if (warp == 0) {
            int n = gcount;
            unsigned ck0 = (lane      < n) ? gbuf[lane]      : 0u;
            unsigned ck1 = (lane + 32 < n) ? gbuf[lane + 32] : 0u;
            bool a0 = (lane < n), a1 = (lane + 32 < n);
            unsigned r = rk;
            unsigned tk = K << bits;
            for (int b = bits - 1; b >= 0; --b) {
                bool bit0 = ((ck0 >> b) & 1u) != 0u;
                bool bit1 = ((ck1 >> b) & 1u) != 0u;
                unsigned c = __popc(__ballot_sync(0xFFFFFFFFu, a0 && bit0))
                           + __popc(__ballot_sync(0xFFFFFFFFu, a1 && bit1));
                if (c >= r) { a0 = a0 && bit0; a1 = a1 && bit1; tk |= (1u << b); }
                else        { r -= c; a0 = a0 && !bit0; a1 = a1 && !bit1; }
            }
            if (lane == 0) sb_t = k2f(tk);
        }
    } else {
        // full 32 raw bits resolved (mass ties) -> threshold value known
        if (tid == 0) sb_t = __uint_as_float(U);
    }
    __syncthreads();
    const float t = sb_t;

    // ---- mask + store: float compare against threshold ----
    float4* po = reinterpret_cast<float4*>(out + base);
#pragma unroll
    for (int s = 0; s < 3; ++s) {
        float4 o;
        float fx = __uint_as_float(u[4*s+0]);
        float fy = __uint_as_float(u[4*s+1]);
        float fz = __uint_as_float(u[4*s+2]);
        float fw = __uint_as_float(u[4*s+3]);
        o.x = (fx < t) ? fx : 0.0f;
        o.y = (fy < t) ? fy : 0.0f;
        o.z = (fz < t) ? fz : 0.0f;
        o.w = (fw < t) ? fw : 0.0f;
        po[tid + s * 256] = o;
    }
    if (tid < 16) {
        uint4 f = urem4[tid];
        float4 o;
        float fx = __uint_as_float(f.x);
        float fy = __uint_as_float(f.y);
        float fz = __uint_as_float(f.z);
        float fw = __uint_as_float(f.w);
        o.x = (fx < t) ? fx : 0.0f;
        o.y = (fy < t) ? fy : 0.0f;
        o.z = (fz < t) ? fz : 0.0f;
        o.w = (fw < t) ? fw : 0.0f;
        po[768 + tid] = o;
    }
}

extern "C" void kernel_launch(void* const* d_in, const int* in_sizes, int n_in,
                              void* d_out, int out_size) {
    const float* x = (const float*)d_in[0];
    float* out = (float*)d_out;
    int rows = in_sizes[0] / NROW;   // 16384
    wta2d_kernel<<<rows, 256>>>(x, out);
}